// round 14
// baseline (speedup 1.0000x reference)
#include <cuda_runtime.h>
#include <cuda_fp16.h>

#define NN 50000
#define EE 800000
#define FK 128          // inner dim
#define C1 192          // agg width pass 1 (128 conv1 + 64 leader)
#define C2 128          // agg width pass 2
#define NC 320          // fused GEMM1 cols: [W1(128) | Wl(64) | Ws(128)]
#define NB 196          // ceil(NN/256)
#define GR1 1480        // gather1 persistent grid (10 blocks/SM x 148)
#define GR2 2368        // gather2 persistent grid (16 blocks/SM x 148)

// ---------------- scratch (device globals; no allocations allowed) -----------
__device__ float g_deg[NN];
__device__ float g_dinv[NN];
__device__ int   g_cnt[NN];
__device__ int   g_rexcl[NN];
__device__ int   g_bsum[NB];
__device__ int   g_boff[NB];
__device__ int   g_rowptr[NN + 1];
__device__ int   g_pos[NN];
__device__ __align__(16) int2   g_csr[EE];            // {src, w*dinv[src] bits}
__device__ __align__(16) __half g_HS1h[NN * C1];      // fp16 GEMM1 out (raw)
__device__ __align__(16) float  g_HSELF[NN * C2];     // x@Ws + bs
__device__ __align__(16) __half g_HNEWh[NN * C2];     // gated fusion (fp16)
__device__ __align__(16) __half g_HS2h[NN * C2];      // fp16 GEMM2 out (raw)

// ---------------- degree / histogram -----------------------------------------
__global__ void k_init() {
    int i = blockIdx.x * blockDim.x + threadIdx.x;
    if (i < NN) { g_deg[i] = 1.0f; g_cnt[i] = 0; }     // self-loop weight 1
}

__global__ void k_deg_hist(const int* __restrict__ ei,
                           const float* __restrict__ ew) {
    int e = blockIdx.x * blockDim.x + threadIdx.x;
    if (e < EE) {
        int d = ei[EE + e];
        atomicAdd(&g_deg[d], ew[e]);
        atomicAdd(&g_cnt[d], 1);
    }
}

// ---------------- hierarchical exclusive scan of g_cnt (+ dinv fold) ---------
__device__ __forceinline__ int block_scan256(int v, int t, int* total) {
    int lane = t & 31, w = t >> 5;
    int x = v;
    #pragma unroll
    for (int o = 1; o < 32; o <<= 1) {
        int y = __shfl_up_sync(0xffffffffu, x, o);
        if (lane >= o) x += y;
    }
    __shared__ int ws[8];
    if (lane == 31) ws[w] = x;
    __syncthreads();
    if (t < 8) {
        int z = ws[t];
        #pragma unroll
        for (int o = 1; o < 8; o <<= 1) {
            int q = __shfl_up_sync(0xffu, z, o);
            if (t >= o) z += q;
        }
        ws[t] = z;
    }
    __syncthreads();
    int woff = (w > 0) ? ws[w - 1] : 0;
    *total = ws[7];
    return woff + x - v;           // exclusive prefix
}

__global__ __launch_bounds__(256) void kA_scan() {
    int b = blockIdx.x, t = threadIdx.x;
    int i = b * 256 + t;
    int v = (i < NN) ? g_cnt[i] : 0;
    int total;
    int excl = block_scan256(v, t, &total);
    if (i < NN) {
        g_rexcl[i] = excl;
        float dg = g_deg[i];
        g_dinv[i] = dg > 0.0f ? rsqrtf(dg) : 0.0f;     // dinv folded here
    }
    if (t == 0) g_bsum[b] = total;
}

__global__ __launch_bounds__(256) void kB_scan() {
    int t = threadIdx.x;
    int v = (t < NB) ? g_bsum[t] : 0;
    int total;
    int excl = block_scan256(v, t, &total);
    if (t < NB) g_boff[t] = excl;
}

__global__ void kC_finalize_ptr() {
    int i = blockIdx.x * blockDim.x + threadIdx.x;
    if (i < NN) {
        int r = g_rexcl[i] + g_boff[i >> 8];
        g_rowptr[i] = r;
        g_pos[i] = r;
    }
    if (i == NN) g_rowptr[NN] = EE;
}

__global__ void k_fill(const int* __restrict__ ei,
                       const float* __restrict__ ew) {
    int e = blockIdx.x * blockDim.x + threadIdx.x;
    if (e < EE) {
        int s = ei[e];
        int d = ei[EE + e];
        int p = atomicAdd(&g_pos[d], 1);
        float w = ew[e] * g_dinv[s];       // fold dinv[src]
        g_csr[p] = make_int2(s, __float_as_int(w));
    }
}

// ---------------- MMA helpers -------------------------------------------------
__device__ __forceinline__ void ldsm_x4(unsigned& r0, unsigned& r1,
                                        unsigned& r2, unsigned& r3,
                                        unsigned addr) {
    asm volatile("ldmatrix.sync.aligned.m8n8.x4.shared.b16 {%0,%1,%2,%3}, [%4];"
                 : "=r"(r0), "=r"(r1), "=r"(r2), "=r"(r3) : "r"(addr));
}
__device__ __forceinline__ void ldsm_x4_t(unsigned& r0, unsigned& r1,
                                          unsigned& r2, unsigned& r3,
                                          unsigned addr) {
    asm volatile("ldmatrix.sync.aligned.m8n8.x4.trans.shared.b16 {%0,%1,%2,%3}, [%4];"
                 : "=r"(r0), "=r"(r1), "=r"(r2), "=r"(r3) : "r"(addr));
}
__device__ __forceinline__ void mma16816(float* c, const unsigned* a,
                                         const unsigned* b) {
    asm volatile(
        "mma.sync.aligned.m16n8k16.row.col.f32.f16.f16.f32 "
        "{%0,%1,%2,%3}, {%4,%5,%6,%7}, {%8,%9}, {%0,%1,%2,%3};"
        : "+f"(c[0]), "+f"(c[1]), "+f"(c[2]), "+f"(c[3])
        : "r"(a[0]), "r"(a[1]), "r"(a[2]), "r"(a[3]), "r"(b[0]), "r"(b[1]));
}
__device__ __forceinline__ unsigned h2u(__half2 h) {
    return *reinterpret_cast<unsigned*>(&h);
}

// ---------------- tensor-core GEMM -------------------------------------------
// mode 1: A fp32, B=[W1|Wl|Ws]; c<192 -> HS1h, c>=192 -> HSELF = v + bs
// mode 2: A fp16 (HNEWh), B=W2; -> HS2h
#define GBM 128
#define GBN 64
__global__ __launch_bounds__(256) void k_gemm_mma(const void* __restrict__ Ap,
                                                  const float* __restrict__ W1p,
                                                  const float* __restrict__ Wlp,
                                                  const float* __restrict__ Wsp,
                                                  int M, int Ncols, int mode,
                                                  const float* __restrict__ bs) {
    extern __shared__ __half smemh[];
    __half* Ah = smemh;                 // [128][128] halves, 16B-unit swizzle
    __half* Bh = smemh + GBM * FK;      // [128][64]

    int tid = threadIdx.x;
    int lane = tid & 31, wid = tid >> 5;
    int warp_m = wid & 3, warp_n = wid >> 2;
    int bm = blockIdx.y * GBM, bn = blockIdx.x * GBN;

    // ---- stage A ----
    if (mode == 1) {
        const float* A = (const float*)Ap;
        #pragma unroll
        for (int l = 0; l < 8; l++) {
            int idx = tid + l * 256;                 // 0..2047
            int row = idx >> 4, u = idx & 15;        // unit = 8 halves
            int gr = bm + row;
            float4 f0 = make_float4(0.f, 0.f, 0.f, 0.f);
            float4 f1 = make_float4(0.f, 0.f, 0.f, 0.f);
            if (gr < M) {
                f0 = *(const float4*)&A[gr * FK + u * 8];
                f1 = *(const float4*)&A[gr * FK + u * 8 + 4];
            }
            uint4 p;
            p.x = h2u(__floats2half2_rn(f0.x, f0.y));
            p.y = h2u(__floats2half2_rn(f0.z, f0.w));
            p.z = h2u(__floats2half2_rn(f1.x, f1.y));
            p.w = h2u(__floats2half2_rn(f1.z, f1.w));
            *(uint4*)&Ah[row * FK + ((u ^ (row & 7)) << 3)] = p;
        }
    } else {
        const __half* A = (const __half*)Ap;
        #pragma unroll
        for (int l = 0; l < 8; l++) {
            int idx = tid + l * 256;
            int row = idx >> 4, u = idx & 15;
            int gr = bm + row;
            uint4 p = make_uint4(0u, 0u, 0u, 0u);
            if (gr < M) p = *(const uint4*)&A[gr * FK + u * 8];
            *(uint4*)&Ah[row * FK + ((u ^ (row & 7)) << 3)] = p;
        }
    }
    // ---- stage B: 128x64 fp32 -> fp16 ----
    #pragma unroll
    for (int l = 0; l < 4; l++) {
        int idx = tid + l * 256;                 // 0..1023
        int row = idx >> 3, u = idx & 7;
        int gc = bn + u * 8;
        float4 f0, f1;
        if (mode == 1) {
            f0 = (gc < 128)      ? *(const float4*)&W1p[row * 128 + gc]
               : (gc < 192)      ? *(const float4*)&Wlp[row * 64 + (gc - 128)]
                                 : *(const float4*)&Wsp[row * 128 + (gc - 192)];
            int gc4 = gc + 4;
            f1 = (gc4 < 128)     ? *(const float4*)&W1p[row * 128 + gc4]
               : (gc4 < 192)     ? *(const float4*)&Wlp[row * 64 + (gc4 - 128)]
                                 : *(const float4*)&Wsp[row * 128 + (gc4 - 192)];
        } else {
            f0 = *(const float4*)&W1p[row * 128 + gc];
            f1 = *(const float4*)&W1p[row * 128 + gc + 4];
        }
        uint4 p;
        p.x = h2u(__floats2half2_rn(f0.x, f0.y));
        p.y = h2u(__floats2half2_rn(f0.z, f0.w));
        p.z = h2u(__floats2half2_rn(f1.x, f1.y));
        p.w = h2u(__floats2half2_rn(f1.z, f1.w));
        *(uint4*)&Bh[row * GBN + ((u ^ (row & 7)) << 3)] = p;
    }
    __syncthreads();

    unsigned aBase = (unsigned)__cvta_generic_to_shared(Ah);
    unsigned bBase = (unsigned)__cvta_generic_to_shared(Bh);

    float acc[2][4][4];
    #pragma unroll
    for (int i = 0; i < 2; i++)
        #pragma unroll
        for (int j = 0; j < 4; j++)
            #pragma unroll
            for (int q = 0; q < 4; q++) acc[i][j][q] = 0.0f;

    #pragma unroll
    for (int kc = 0; kc < 8; kc++) {
        int k0 = kc * 16;
        unsigned afr[2][4], bfr[4][2];
        #pragma unroll
        for (int mt = 0; mt < 2; mt++) {
            int lrow = warp_m * 32 + mt * 16 + (lane & 15);
            int lu = (k0 >> 3) + (lane >> 4);
            unsigned addr = aBase + (unsigned)((lrow * FK + ((lu ^ (lrow & 7)) << 3)) * 2);
            ldsm_x4(afr[mt][0], afr[mt][1], afr[mt][2], afr[mt][3], addr);
        }
        #pragma unroll
        for (int np = 0; np < 2; np++) {
            int nb = warp_n * 32 + np * 16;
            int brow = k0 + (lane & 15);
            int bu = (nb >> 3) + (lane >> 4);
            unsigned addr = bBase + (unsigned)((brow * GBN + ((bu ^ (brow & 7)) << 3)) * 2);
            unsigned r0, r1, r2, r3;
            ldsm_x4_t(r0, r1, r2, r3, addr);
            bfr[np * 2][0] = r0;     bfr[np * 2][1] = r1;
            bfr[np * 2 + 1][0] = r2; bfr[np * 2 + 1][1] = r3;
        }
        #pragma unroll
        for (int mt = 0; mt < 2; mt++)
            #pragma unroll
            for (int nt = 0; nt < 4; nt++)
                mma16816(acc[mt][nt], afr[mt], bfr[nt]);
    }

    // ---- epilogue ----
    #pragma unroll
    for (int mt = 0; mt < 2; mt++) {
        int r0 = bm + warp_m * 32 + mt * 16 + (lane >> 2);
        int r1 = r0 + 8;
        #pragma unroll
        for (int nt = 0; nt < 4; nt++) {
            int col = bn + warp_n * 32 + nt * 8 + (lane & 3) * 2;
            float* c = acc[mt][nt];
            if (mode == 1) {
                if (col < C1) {
                    if (r0 < M) *(unsigned*)&g_HS1h[r0 * C1 + col] =
                        h2u(__floats2half2_rn(c[0], c[1]));
                    if (r1 < M) *(unsigned*)&g_HS1h[r1 * C1 + col] =
                        h2u(__floats2half2_rn(c[2], c[3]));
                } else {
                    int cc = col - C1;
                    float bsv0 = bs[cc], bsv1 = bs[cc + 1];
                    if (r0 < M) {
                        g_HSELF[r0 * C2 + cc] = c[0] + bsv0;
                        g_HSELF[r0 * C2 + cc + 1] = c[1] + bsv1;
                    }
                    if (r1 < M) {
                        g_HSELF[r1 * C2 + cc] = c[2] + bsv0;
                        g_HSELF[r1 * C2 + cc + 1] = c[3] + bsv1;
                    }
                }
            } else {
                if (r0 < M) *(unsigned*)&g_HS2h[r0 * C2 + col] =
                    h2u(__floats2half2_rn(c[0], c[1]));
                if (r1 < M) *(unsigned*)&g_HS2h[r1 * C2 + col] =
                    h2u(__floats2half2_rn(c[2], c[3]));
            }
        }
    }
}

// ---------------- gather pass 1: PERSISTENT row loop -------------------------
// 192 threads: slot = t/96 (3 warps each), cg = t%96 covers 192 cols as half2.
// Grid = GR1 (one wave); each block strides rows -> no wave transitions.
__global__ __launch_bounds__(192) void k_gather1(const float* __restrict__ b1,
                                                 const float* __restrict__ bl,
                                                 const float* __restrict__ Wl2,
                                                 const float* __restrict__ bl2,
                                                 float* __restrict__ out) {
    __shared__ int    s_src[192];
    __shared__ float  s_w[192];
    __shared__ float2 s_red[96];
    __shared__ float  s_agg[192];
    __shared__ float  s_part[2];
    __shared__ float  s_ls;
    int t = threadIdx.x;
    int slot = t / 96, cg = t - slot * 96;

    for (int row = blockIdx.x; row < NN; row += GR1) {
        int beg = g_rowptr[row], end = g_rowptr[row + 1];
        float di = g_dinv[row];
        float ax = 0.0f, ay = 0.0f;
        if (slot == 0) {
            float2 f = __half22float2(*(const __half2*)&g_HS1h[row * C1 + cg * 2]);
            ax = di * f.x; ay = di * f.y;          // self term
        }

        for (int chunk = beg; chunk < end; chunk += 192) {
            int m = min(192, end - chunk);
            __syncthreads();
            if (t < m) {
                int2 e = g_csr[chunk + t];
                s_src[t] = e.x;
                s_w[t] = __int_as_float(e.y);
            }
            __syncthreads();
            #pragma unroll 4
            for (int j = slot; j < m; j += 2) {
                float w = s_w[j];
                float2 f = __half22float2(
                    *(const __half2*)&g_HS1h[s_src[j] * C1 + cg * 2]);
                ax = fmaf(w, f.x, ax); ay = fmaf(w, f.y, ay);
            }
        }
        __syncthreads();
        if (slot == 1) s_red[cg] = make_float2(ax, ay);
        __syncthreads();
        if (slot == 0) {
            float2 o = s_red[cg];
            s_agg[cg * 2] = ax + o.x;
            s_agg[cg * 2 + 1] = ay + o.y;
        }
        __syncthreads();

        if (t >= 128) {                        // leader branch (warps 4,5)
            float r = fmaxf(di * s_agg[t] + bl[t - 128], 0.0f);
            float p = r * Wl2[t - 128];
            #pragma unroll
            for (int o = 16; o > 0; o >>= 1)
                p += __shfl_down_sync(0xffffffffu, p, o);
            if ((t & 31) == 0) s_part[(t - 128) >> 5] = p;
        }
        __syncthreads();
        if (t == 0) {
            float z = s_part[0] + s_part[1] + bl2[0];
            float ls = 1.0f / (1.0f + expf(-z));
            s_ls = ls;
            out[NN * 128 + row] = ls;          // leader_score output
        }
        __syncthreads();
        if (t < 128) {
            float hn = fmaxf(di * s_agg[t] + b1[t], 0.0f);
            float ls = s_ls;
            float v = (1.0f - ls) * hn + ls * g_HSELF[row * C2 + t];
            g_HNEWh[row * C2 + t] = __float2half(v);
        }
    }
}

// ---------------- gather pass 2: PERSISTENT row loop -------------------------
// 128 threads: slot = t>>6 (2 warps each), cg = t&63 covers 128 cols as half2.
__global__ __launch_bounds__(128) void k_gather2(const float* __restrict__ b2,
                                                 float* __restrict__ out) {
    __shared__ int    s_src[128];
    __shared__ float  s_w[128];
    __shared__ float2 s_red[64];
    int t = threadIdx.x;
    int slot = t >> 6, cg = t & 63;

    for (int row = blockIdx.x; row < NN; row += GR2) {
        int beg = g_rowptr[row], end = g_rowptr[row + 1];
        float di = g_dinv[row];
        float ax = 0.0f, ay = 0.0f;
        if (slot == 0) {
            float2 f = __half22float2(*(const __half2*)&g_HS2h[row * C2 + cg * 2]);
            ax = di * f.x; ay = di * f.y;
        }

        for (int chunk = beg; chunk < end; chunk += 128) {
            int m = min(128, end - chunk);
            __syncthreads();
            if (t < m) {
                int2 e = g_csr[chunk + t];
                s_src[t] = e.x;
                s_w[t] = __int_as_float(e.y);
            }
            __syncthreads();
            #pragma unroll 4
            for (int j = slot; j < m; j += 2) {
                float w = s_w[j];
                float2 f = __half22float2(
                    *(const __half2*)&g_HS2h[s_src[j] * C2 + cg * 2]);
                ax = fmaf(w, f.x, ax); ay = fmaf(w, f.y, ay);
            }
        }
        __syncthreads();
        if (slot == 1) s_red[cg] = make_float2(ax, ay);
        __syncthreads();
        if (slot == 0) {
            float2 o = s_red[cg];
            float2 r;
            r.x = fmaxf(di * (ax + o.x) + b2[cg * 2], 0.0f);
            r.y = fmaxf(di * (ay + o.y) + b2[cg * 2 + 1], 0.0f);
            *(float2*)&out[row * C2 + cg * 2] = r;
        }
    }
}

// ---------------- launch ------------------------------------------------------
extern "C" void kernel_launch(void* const* d_in, const int* in_sizes, int n_in,
                              void* d_out, int out_size) {
    const float* x   = (const float*)d_in[0];
    const int*   ei  = (const int*)d_in[1];        // int32 (JAX x64 disabled)
    const float* ew  = (const float*)d_in[2];
    const float* W1  = (const float*)d_in[3];
    const float* b1  = (const float*)d_in[4];
    const float* W2  = (const float*)d_in[5];
    const float* b2  = (const float*)d_in[6];
    const float* Ws  = (const float*)d_in[7];
    const float* bs  = (const float*)d_in[8];
    const float* Wl  = (const float*)d_in[9];
    const float* bl  = (const float*)d_in[10];
    const float* Wl2 = (const float*)d_in[11];
    const float* bl2 = (const float*)d_in[12];
    float* out = (float*)d_out;

    __half* gHNEWh; cudaGetSymbolAddress((void**)&gHNEWh, g_HNEWh);

    const int SMEM_GEMM = (GBM * FK + FK * GBN) * 2;   // 49152 B

    static cudaStream_t s2 = nullptr;
    static cudaEvent_t evFork = nullptr, evJoin = nullptr;
    if (s2 == nullptr) {
        cudaStreamCreateWithFlags(&s2, cudaStreamNonBlocking);
        cudaEventCreateWithFlags(&evFork, cudaEventDisableTiming);
        cudaEventCreateWithFlags(&evJoin, cudaEventDisableTiming);
        cudaFuncSetAttribute(k_gemm_mma,
                             cudaFuncAttributeMaxDynamicSharedMemorySize,
                             SMEM_GEMM);
    }

    // fork
    cudaEventRecord(evFork, 0);
    cudaStreamWaitEvent(s2, evFork, 0);

    // side stream preproc, main stream GEMM1 in parallel
    k_init<<<(NN + 255) / 256, 256, 0, s2>>>();
    k_deg_hist<<<(EE + 255) / 256, 256, 0, s2>>>(ei, ew);
    kA_scan<<<NB, 256, 0, s2>>>();                       // + dinv fold

    {   // GEMM1: x @ [W1|Wl|Ws] — tensor cores
        dim3 grid(NC / GBN, (NN + GBM - 1) / GBM);
        k_gemm_mma<<<grid, 256, SMEM_GEMM>>>(x, W1, Wl, Ws, NN, NC, 1, bs);
    }

    kB_scan<<<1, 256, 0, s2>>>();
    kC_finalize_ptr<<<(NN + 256) / 256, 256, 0, s2>>>();
    k_fill<<<(EE + 255) / 256, 256, 0, s2>>>(ei, ew);
    cudaEventRecord(evJoin, s2);
    cudaStreamWaitEvent(0, evJoin, 0);

    // gather 1 (persistent; fused relu, leader score, gate; fp16 HNEW)
    k_gather1<<<GR1, 192>>>(b1, bl, Wl2, bl2, out);

    // GEMM2: h_new(fp16) @ W2 — tensor cores
    {
        dim3 grid(C2 / GBN, (NN + GBM - 1) / GBM);
        k_gemm_mma<<<grid, 256, SMEM_GEMM>>>(gHNEWh, W2, W2, W2, NN, C2, 2, nullptr);
    }

    // gather 2 (persistent; fused final relu)
    k_gather2<<<GR2, 128>>>(b2, out);
}

// round 15
// speedup vs baseline: 1.3707x; 1.3707x over previous
#include <cuda_runtime.h>
#include <cuda_fp16.h>

#define NN 50000
#define EE 800000
#define FK 128          // inner dim
#define C1 192          // agg width pass 1 (128 conv1 + 64 leader)
#define C2 128          // agg width pass 2
#define NC 320          // fused GEMM1 cols: [W1(128) | Wl(64) | Ws(128)]
#define NB 196          // ceil(NN/256)

// ---------------- scratch (device globals; no allocations allowed) -----------
__device__ float g_deg[NN];
__device__ float g_dinv[NN];
__device__ int   g_cnt[NN];
__device__ int   g_rexcl[NN];
__device__ int   g_bsum[NB];
__device__ int   g_boff[NB];
__device__ int   g_rowptr[NN + 1];
__device__ int   g_pos[NN];
__device__ __align__(16) int2   g_csr[EE];            // {src, w*dinv[src] bits}
__device__ __align__(16) __half g_HS1h[NN * C1];      // fp16 GEMM1 out (raw)
__device__ __align__(16) float  g_HSELF[NN * C2];     // x@Ws + bs
__device__ __align__(16) __half g_HNEWh[NN * C2];     // gated fusion (fp16)
__device__ __align__(16) __half g_HS2h[NN * C2];      // fp16 GEMM2 out (raw)

// ---------------- degree / histogram -----------------------------------------
__global__ void k_init() {
    int i = blockIdx.x * blockDim.x + threadIdx.x;
    if (i < NN) { g_deg[i] = 1.0f; g_cnt[i] = 0; }     // self-loop weight 1
}

__global__ void k_deg_hist(const int* __restrict__ ei,
                           const float* __restrict__ ew) {
    int e = blockIdx.x * blockDim.x + threadIdx.x;
    if (e < EE) {
        int d = ei[EE + e];
        atomicAdd(&g_deg[d], ew[e]);
        atomicAdd(&g_cnt[d], 1);
    }
}

// ---------------- hierarchical exclusive scan of g_cnt (+ dinv fold) ---------
__device__ __forceinline__ int block_scan256(int v, int t, int* total) {
    int lane = t & 31, w = t >> 5;
    int x = v;
    #pragma unroll
    for (int o = 1; o < 32; o <<= 1) {
        int y = __shfl_up_sync(0xffffffffu, x, o);
        if (lane >= o) x += y;
    }
    __shared__ int ws[8];
    if (lane == 31) ws[w] = x;
    __syncthreads();
    if (t < 8) {
        int z = ws[t];
        #pragma unroll
        for (int o = 1; o < 8; o <<= 1) {
            int q = __shfl_up_sync(0xffu, z, o);
            if (t >= o) z += q;
        }
        ws[t] = z;
    }
    __syncthreads();
    int woff = (w > 0) ? ws[w - 1] : 0;
    *total = ws[7];
    return woff + x - v;           // exclusive prefix
}

__global__ __launch_bounds__(256) void kA_scan() {
    int b = blockIdx.x, t = threadIdx.x;
    int i = b * 256 + t;
    int v = (i < NN) ? g_cnt[i] : 0;
    int total;
    int excl = block_scan256(v, t, &total);
    if (i < NN) {
        g_rexcl[i] = excl;
        float dg = g_deg[i];
        g_dinv[i] = dg > 0.0f ? rsqrtf(dg) : 0.0f;     // dinv folded here
    }
    if (t == 0) g_bsum[b] = total;
}

__global__ __launch_bounds__(256) void kB_scan() {
    int t = threadIdx.x;
    int v = (t < NB) ? g_bsum[t] : 0;
    int total;
    int excl = block_scan256(v, t, &total);
    if (t < NB) g_boff[t] = excl;
}

__global__ void kC_finalize_ptr() {
    int i = blockIdx.x * blockDim.x + threadIdx.x;
    if (i < NN) {
        int r = g_rexcl[i] + g_boff[i >> 8];
        g_rowptr[i] = r;
        g_pos[i] = r;
    }
    if (i == NN) g_rowptr[NN] = EE;
}

__global__ void k_fill(const int* __restrict__ ei,
                       const float* __restrict__ ew) {
    int e = blockIdx.x * blockDim.x + threadIdx.x;
    if (e < EE) {
        int s = ei[e];
        int d = ei[EE + e];
        int p = atomicAdd(&g_pos[d], 1);
        float w = ew[e] * g_dinv[s];       // fold dinv[src]
        g_csr[p] = make_int2(s, __float_as_int(w));
    }
}

// ---------------- MMA helpers -------------------------------------------------
__device__ __forceinline__ void ldsm_x4(unsigned& r0, unsigned& r1,
                                        unsigned& r2, unsigned& r3,
                                        unsigned addr) {
    asm volatile("ldmatrix.sync.aligned.m8n8.x4.shared.b16 {%0,%1,%2,%3}, [%4];"
                 : "=r"(r0), "=r"(r1), "=r"(r2), "=r"(r3) : "r"(addr));
}
__device__ __forceinline__ void ldsm_x4_t(unsigned& r0, unsigned& r1,
                                          unsigned& r2, unsigned& r3,
                                          unsigned addr) {
    asm volatile("ldmatrix.sync.aligned.m8n8.x4.trans.shared.b16 {%0,%1,%2,%3}, [%4];"
                 : "=r"(r0), "=r"(r1), "=r"(r2), "=r"(r3) : "r"(addr));
}
__device__ __forceinline__ void mma16816(float* c, const unsigned* a,
                                         const unsigned* b) {
    asm volatile(
        "mma.sync.aligned.m16n8k16.row.col.f32.f16.f16.f32 "
        "{%0,%1,%2,%3}, {%4,%5,%6,%7}, {%8,%9}, {%0,%1,%2,%3};"
        : "+f"(c[0]), "+f"(c[1]), "+f"(c[2]), "+f"(c[3])
        : "r"(a[0]), "r"(a[1]), "r"(a[2]), "r"(a[3]), "r"(b[0]), "r"(b[1]));
}
__device__ __forceinline__ unsigned h2u(__half2 h) {
    return *reinterpret_cast<unsigned*>(&h);
}

// ---------------- tensor-core GEMM -------------------------------------------
// mode 1: A fp32, B=[W1|Wl|Ws]; c<192 -> HS1h, c>=192 -> HSELF = v + bs
// mode 2: A fp16 (HNEWh), B=W2; -> HS2h
#define GBM 128
#define GBN 64
__global__ __launch_bounds__(256) void k_gemm_mma(const void* __restrict__ Ap,
                                                  const float* __restrict__ W1p,
                                                  const float* __restrict__ Wlp,
                                                  const float* __restrict__ Wsp,
                                                  int M, int Ncols, int mode,
                                                  const float* __restrict__ bs) {
    extern __shared__ __half smemh[];
    __half* Ah = smemh;                 // [128][128] halves, 16B-unit swizzle
    __half* Bh = smemh + GBM * FK;      // [128][64]

    int tid = threadIdx.x;
    int lane = tid & 31, wid = tid >> 5;
    int warp_m = wid & 3, warp_n = wid >> 2;
    int bm = blockIdx.y * GBM, bn = blockIdx.x * GBN;

    // ---- stage A ----
    if (mode == 1) {
        const float* A = (const float*)Ap;
        #pragma unroll
        for (int l = 0; l < 8; l++) {
            int idx = tid + l * 256;                 // 0..2047
            int row = idx >> 4, u = idx & 15;        // unit = 8 halves
            int gr = bm + row;
            float4 f0 = make_float4(0.f, 0.f, 0.f, 0.f);
            float4 f1 = make_float4(0.f, 0.f, 0.f, 0.f);
            if (gr < M) {
                f0 = *(const float4*)&A[gr * FK + u * 8];
                f1 = *(const float4*)&A[gr * FK + u * 8 + 4];
            }
            uint4 p;
            p.x = h2u(__floats2half2_rn(f0.x, f0.y));
            p.y = h2u(__floats2half2_rn(f0.z, f0.w));
            p.z = h2u(__floats2half2_rn(f1.x, f1.y));
            p.w = h2u(__floats2half2_rn(f1.z, f1.w));
            *(uint4*)&Ah[row * FK + ((u ^ (row & 7)) << 3)] = p;
        }
    } else {
        const __half* A = (const __half*)Ap;
        #pragma unroll
        for (int l = 0; l < 8; l++) {
            int idx = tid + l * 256;
            int row = idx >> 4, u = idx & 15;
            int gr = bm + row;
            uint4 p = make_uint4(0u, 0u, 0u, 0u);
            if (gr < M) p = *(const uint4*)&A[gr * FK + u * 8];
            *(uint4*)&Ah[row * FK + ((u ^ (row & 7)) << 3)] = p;
        }
    }
    // ---- stage B: 128x64 fp32 -> fp16 ----
    #pragma unroll
    for (int l = 0; l < 4; l++) {
        int idx = tid + l * 256;                 // 0..1023
        int row = idx >> 3, u = idx & 7;
        int gc = bn + u * 8;
        float4 f0, f1;
        if (mode == 1) {
            f0 = (gc < 128)      ? *(const float4*)&W1p[row * 128 + gc]
               : (gc < 192)      ? *(const float4*)&Wlp[row * 64 + (gc - 128)]
                                 : *(const float4*)&Wsp[row * 128 + (gc - 192)];
            int gc4 = gc + 4;
            f1 = (gc4 < 128)     ? *(const float4*)&W1p[row * 128 + gc4]
               : (gc4 < 192)     ? *(const float4*)&Wlp[row * 64 + (gc4 - 128)]
                                 : *(const float4*)&Wsp[row * 128 + (gc4 - 192)];
        } else {
            f0 = *(const float4*)&W1p[row * 128 + gc];
            f1 = *(const float4*)&W1p[row * 128 + gc + 4];
        }
        uint4 p;
        p.x = h2u(__floats2half2_rn(f0.x, f0.y));
        p.y = h2u(__floats2half2_rn(f0.z, f0.w));
        p.z = h2u(__floats2half2_rn(f1.x, f1.y));
        p.w = h2u(__floats2half2_rn(f1.z, f1.w));
        *(uint4*)&Bh[row * GBN + ((u ^ (row & 7)) << 3)] = p;
    }
    __syncthreads();

    unsigned aBase = (unsigned)__cvta_generic_to_shared(Ah);
    unsigned bBase = (unsigned)__cvta_generic_to_shared(Bh);

    float acc[2][4][4];
    #pragma unroll
    for (int i = 0; i < 2; i++)
        #pragma unroll
        for (int j = 0; j < 4; j++)
            #pragma unroll
            for (int q = 0; q < 4; q++) acc[i][j][q] = 0.0f;

    #pragma unroll
    for (int kc = 0; kc < 8; kc++) {
        int k0 = kc * 16;
        unsigned afr[2][4], bfr[4][2];
        #pragma unroll
        for (int mt = 0; mt < 2; mt++) {
            int lrow = warp_m * 32 + mt * 16 + (lane & 15);
            int lu = (k0 >> 3) + (lane >> 4);
            unsigned addr = aBase + (unsigned)((lrow * FK + ((lu ^ (lrow & 7)) << 3)) * 2);
            ldsm_x4(afr[mt][0], afr[mt][1], afr[mt][2], afr[mt][3], addr);
        }
        #pragma unroll
        for (int np = 0; np < 2; np++) {
            int nb = warp_n * 32 + np * 16;
            int brow = k0 + (lane & 15);
            int bu = (nb >> 3) + (lane >> 4);
            unsigned addr = bBase + (unsigned)((brow * GBN + ((bu ^ (brow & 7)) << 3)) * 2);
            unsigned r0, r1, r2, r3;
            ldsm_x4_t(r0, r1, r2, r3, addr);
            bfr[np * 2][0] = r0;     bfr[np * 2][1] = r1;
            bfr[np * 2 + 1][0] = r2; bfr[np * 2 + 1][1] = r3;
        }
        #pragma unroll
        for (int mt = 0; mt < 2; mt++)
            #pragma unroll
            for (int nt = 0; nt < 4; nt++)
                mma16816(acc[mt][nt], afr[mt], bfr[nt]);
    }

    // ---- epilogue ----
    #pragma unroll
    for (int mt = 0; mt < 2; mt++) {
        int r0 = bm + warp_m * 32 + mt * 16 + (lane >> 2);
        int r1 = r0 + 8;
        #pragma unroll
        for (int nt = 0; nt < 4; nt++) {
            int col = bn + warp_n * 32 + nt * 8 + (lane & 3) * 2;
            float* c = acc[mt][nt];
            if (mode == 1) {
                if (col < C1) {
                    if (r0 < M) *(unsigned*)&g_HS1h[r0 * C1 + col] =
                        h2u(__floats2half2_rn(c[0], c[1]));
                    if (r1 < M) *(unsigned*)&g_HS1h[r1 * C1 + col] =
                        h2u(__floats2half2_rn(c[2], c[3]));
                } else {
                    int cc = col - C1;
                    float bsv0 = bs[cc], bsv1 = bs[cc + 1];
                    if (r0 < M) {
                        g_HSELF[r0 * C2 + cc] = c[0] + bsv0;
                        g_HSELF[r0 * C2 + cc + 1] = c[1] + bsv1;
                    }
                    if (r1 < M) {
                        g_HSELF[r1 * C2 + cc] = c[2] + bsv0;
                        g_HSELF[r1 * C2 + cc + 1] = c[3] + bsv1;
                    }
                }
            } else {
                if (r0 < M) *(unsigned*)&g_HS2h[r0 * C2 + col] =
                    h2u(__floats2half2_rn(c[0], c[1]));
                if (r1 < M) *(unsigned*)&g_HS2h[r1 * C2 + col] =
                    h2u(__floats2half2_rn(c[2], c[3]));
            }
        }
    }
}

// ---------------- gather pass 1: 96 threads, thread t owns cols 2t,2t+1 ------
// 3 warps/block -> 21 blocks/SM. Threads 0-63 = conv1 cols, 64-95 = leader
// cols (= warp 2 exactly: leader reduction is one warp shuffle).
__global__ __launch_bounds__(96) void k_gather1(const float* __restrict__ b1,
                                                const float* __restrict__ bl,
                                                const float* __restrict__ Wl2,
                                                const float* __restrict__ bl2,
                                                float* __restrict__ out) {
    __shared__ int   s_src[96];
    __shared__ float s_w[96];
    __shared__ float s_ls;
    int row = blockIdx.x;
    int t = threadIdx.x;
    int beg = g_rowptr[row], end = g_rowptr[row + 1];

    float di = g_dinv[row];
    float2 f0 = __half22float2(*(const __half2*)&g_HS1h[row * C1 + t * 2]);
    float ax = di * f0.x, ay = di * f0.y;          // self term

    for (int chunk = beg; chunk < end; chunk += 96) {
        int m = min(96, end - chunk);
        __syncthreads();
        if (t < m) {
            int2 e = g_csr[chunk + t];
            s_src[t] = e.x;
            s_w[t] = __int_as_float(e.y);
        }
        __syncthreads();
        #pragma unroll 4
        for (int j = 0; j < m; j++) {
            float w = s_w[j];
            float2 f = __half22float2(
                *(const __half2*)&g_HS1h[s_src[j] * C1 + t * 2]);
            ax = fmaf(w, f.x, ax); ay = fmaf(w, f.y, ay);
        }
    }

    if (t >= 64) {                                 // leader cols (warp 2)
        int c = t - 64;                            // 0..31 -> cols 128+2c
        float rx = fmaxf(di * ax + bl[2 * c], 0.0f);
        float ry = fmaxf(di * ay + bl[2 * c + 1], 0.0f);
        float p = rx * Wl2[2 * c] + ry * Wl2[2 * c + 1];
        #pragma unroll
        for (int o = 16; o > 0; o >>= 1)
            p += __shfl_down_sync(0xffffffffu, p, o);
        if (c == 0) {
            float z = p + bl2[0];
            float ls = 1.0f / (1.0f + expf(-z));
            s_ls = ls;
            out[NN * 128 + row] = ls;              // leader_score output
        }
    }
    __syncthreads();
    if (t < 64) {                                  // conv1 cols -> HNEW
        float ls = s_ls;
        float hn0 = fmaxf(di * ax + b1[2 * t], 0.0f);
        float hn1 = fmaxf(di * ay + b1[2 * t + 1], 0.0f);
        float2 hs = *(const float2*)&g_HSELF[row * C2 + 2 * t];
        float v0 = (1.0f - ls) * hn0 + ls * hs.x;
        float v1 = (1.0f - ls) * hn1 + ls * hs.y;
        *(__half2*)&g_HNEWh[row * C2 + 2 * t] = __floats2half2_rn(v0, v1);
    }
}

// ---------------- gather pass 2: 64 threads, thread t owns cols 2t,2t+1 ------
// 2 warps/block -> 32 blocks/SM (CTA cap). No cross-thread reduction.
__global__ __launch_bounds__(64) void k_gather2(const float* __restrict__ b2,
                                                float* __restrict__ out) {
    __shared__ int   s_src[64];
    __shared__ float s_w[64];
    int row = blockIdx.x;
    int t = threadIdx.x;
    int beg = g_rowptr[row], end = g_rowptr[row + 1];

    float di = g_dinv[row];
    float2 f0 = __half22float2(*(const __half2*)&g_HS2h[row * C2 + t * 2]);
    float ax = di * f0.x, ay = di * f0.y;

    for (int chunk = beg; chunk < end; chunk += 64) {
        int m = min(64, end - chunk);
        __syncthreads();
        if (t < m) {
            int2 e = g_csr[chunk + t];
            s_src[t] = e.x;
            s_w[t] = __int_as_float(e.y);
        }
        __syncthreads();
        #pragma unroll 4
        for (int j = 0; j < m; j++) {
            float w = s_w[j];
            float2 f = __half22float2(
                *(const __half2*)&g_HS2h[s_src[j] * C2 + t * 2]);
            ax = fmaf(w, f.x, ax); ay = fmaf(w, f.y, ay);
        }
    }

    float2 r;
    r.x = fmaxf(di * ax + b2[2 * t], 0.0f);
    r.y = fmaxf(di * ay + b2[2 * t + 1], 0.0f);
    *(float2*)&out[row * C2 + 2 * t] = r;
}

// ---------------- launch ------------------------------------------------------
extern "C" void kernel_launch(void* const* d_in, const int* in_sizes, int n_in,
                              void* d_out, int out_size) {
    const float* x   = (const float*)d_in[0];
    const int*   ei  = (const int*)d_in[1];        // int32 (JAX x64 disabled)
    const float* ew  = (const float*)d_in[2];
    const float* W1  = (const float*)d_in[3];
    const float* b1  = (const float*)d_in[4];
    const float* W2  = (const float*)d_in[5];
    const float* b2  = (const float*)d_in[6];
    const float* Ws  = (const float*)d_in[7];
    const float* bs  = (const float*)d_in[8];
    const float* Wl  = (const float*)d_in[9];
    const float* bl  = (const float*)d_in[10];
    const float* Wl2 = (const float*)d_in[11];
    const float* bl2 = (const float*)d_in[12];
    float* out = (float*)d_out;

    __half* gHNEWh; cudaGetSymbolAddress((void**)&gHNEWh, g_HNEWh);

    const int SMEM_GEMM = (GBM * FK + FK * GBN) * 2;   // 49152 B

    static cudaStream_t s2 = nullptr;
    static cudaEvent_t evFork = nullptr, evJoin = nullptr;
    if (s2 == nullptr) {
        cudaStreamCreateWithFlags(&s2, cudaStreamNonBlocking);
        cudaEventCreateWithFlags(&evFork, cudaEventDisableTiming);
        cudaEventCreateWithFlags(&evJoin, cudaEventDisableTiming);
        cudaFuncSetAttribute(k_gemm_mma,
                             cudaFuncAttributeMaxDynamicSharedMemorySize,
                             SMEM_GEMM);
    }

    // fork
    cudaEventRecord(evFork, 0);
    cudaStreamWaitEvent(s2, evFork, 0);

    // side stream preproc, main stream GEMM1 in parallel
    k_init<<<(NN + 255) / 256, 256, 0, s2>>>();
    k_deg_hist<<<(EE + 255) / 256, 256, 0, s2>>>(ei, ew);
    kA_scan<<<NB, 256, 0, s2>>>();                       // + dinv fold

    {   // GEMM1: x @ [W1|Wl|Ws] — tensor cores
        dim3 grid(NC / GBN, (NN + GBM - 1) / GBM);
        k_gemm_mma<<<grid, 256, SMEM_GEMM>>>(x, W1, Wl, Ws, NN, NC, 1, bs);
    }

    kB_scan<<<1, 256, 0, s2>>>();
    kC_finalize_ptr<<<(NN + 256) / 256, 256, 0, s2>>>();
    k_fill<<<(EE + 255) / 256, 256, 0, s2>>>(ei, ew);
    cudaEventRecord(evJoin, s2);
    cudaStreamWaitEvent(0, evJoin, 0);

    // gather 1 (96 thr/row; fused relu, leader score, gate; fp16 HNEW)
    k_gather1<<<NN, 96>>>(b1, bl, Wl2, bl2, out);

    // GEMM2: h_new(fp16) @ W2 — tensor cores
    {
        dim3 grid(C2 / GBN, (NN + GBM - 1) / GBM);
        k_gemm_mma<<<grid, 256, SMEM_GEMM>>>(gHNEWh, W2, W2, W2, NN, C2, 2, nullptr);
    }

    // gather 2 (64 thr/row; fused final relu)
    k_gather2<<<NN, 64>>>(b2, out);
}

// round 16
// speedup vs baseline: 1.4195x; 1.0356x over previous
#include <cuda_runtime.h>
#include <cuda_fp16.h>

#define NN 50000
#define EE 800000
#define FK 128          // inner dim
#define C1 192          // agg width pass 1 (128 conv1 + 64 leader)
#define C2 128          // agg width pass 2
#define NC 320          // fused GEMM1 cols: [W1(128) | Wl(64) | Ws(128)]
#define NB 196          // ceil(NN/256)

// ---------------- scratch (device globals; no allocations allowed) -----------
__device__ float g_deg[NN];
__device__ float g_dinv[NN];
__device__ int   g_cnt[NN];
__device__ int   g_rexcl[NN];
__device__ int   g_bsum[NB];
__device__ int   g_boff[NB];
__device__ __align__(8) int2 g_rowpair[NN];           // {beg, end} per row
__device__ int   g_pos[NN];
__device__ __align__(16) int2   g_csr[EE];            // {src, w*dinv[src] bits}
__device__ __align__(16) __half g_HS1h[NN * C1];      // fp16 GEMM1 out (raw)
__device__ __align__(16) __half g_HSELFh[NN * C2];    // x@Ws + bs (fp16)
__device__ __align__(16) __half g_HNEWh[NN * C2];     // gated fusion (fp16)
__device__ __align__(16) __half g_HS2h[NN * C2];      // fp16 GEMM2 out (raw)

// ---------------- degree / histogram -----------------------------------------
__global__ void k_init() {
    int i = blockIdx.x * blockDim.x + threadIdx.x;
    if (i < NN) { g_deg[i] = 1.0f; g_cnt[i] = 0; }     // self-loop weight 1
}

__global__ void k_deg_hist(const int* __restrict__ ei,
                           const float* __restrict__ ew) {
    int e = blockIdx.x * blockDim.x + threadIdx.x;
    if (e < EE) {
        int d = ei[EE + e];
        atomicAdd(&g_deg[d], ew[e]);
        atomicAdd(&g_cnt[d], 1);
    }
}

// ---------------- hierarchical exclusive scan of g_cnt (+ dinv fold) ---------
__device__ __forceinline__ int block_scan256(int v, int t, int* total) {
    int lane = t & 31, w = t >> 5;
    int x = v;
    #pragma unroll
    for (int o = 1; o < 32; o <<= 1) {
        int y = __shfl_up_sync(0xffffffffu, x, o);
        if (lane >= o) x += y;
    }
    __shared__ int ws[8];
    if (lane == 31) ws[w] = x;
    __syncthreads();
    if (t < 8) {
        int z = ws[t];
        #pragma unroll
        for (int o = 1; o < 8; o <<= 1) {
            int q = __shfl_up_sync(0xffu, z, o);
            if (t >= o) z += q;
        }
        ws[t] = z;
    }
    __syncthreads();
    int woff = (w > 0) ? ws[w - 1] : 0;
    *total = ws[7];
    return woff + x - v;           // exclusive prefix
}

__global__ __launch_bounds__(256) void kA_scan() {
    int b = blockIdx.x, t = threadIdx.x;
    int i = b * 256 + t;
    int v = (i < NN) ? g_cnt[i] : 0;
    int total;
    int excl = block_scan256(v, t, &total);
    if (i < NN) {
        g_rexcl[i] = excl;
        float dg = g_deg[i];
        g_dinv[i] = dg > 0.0f ? rsqrtf(dg) : 0.0f;     // dinv folded here
    }
    if (t == 0) g_bsum[b] = total;
}

__global__ __launch_bounds__(256) void kB_scan() {
    int t = threadIdx.x;
    int v = (t < NB) ? g_bsum[t] : 0;
    int total;
    int excl = block_scan256(v, t, &total);
    if (t < NB) g_boff[t] = excl;
}

__global__ void kC_finalize_ptr() {
    int i = blockIdx.x * blockDim.x + threadIdx.x;
    if (i < NN) {
        int r = g_rexcl[i] + g_boff[i >> 8];
        g_rowpair[i].x = r;
        if (i > 0) g_rowpair[i - 1].y = r;
        if (i == NN - 1) g_rowpair[NN - 1].y = EE;
        g_pos[i] = r;
    }
}

__global__ void k_fill(const int* __restrict__ ei,
                       const float* __restrict__ ew) {
    int e = blockIdx.x * blockDim.x + threadIdx.x;
    if (e < EE) {
        int s = ei[e];
        int d = ei[EE + e];
        int p = atomicAdd(&g_pos[d], 1);
        float w = ew[e] * g_dinv[s];       // fold dinv[src]
        g_csr[p] = make_int2(s, __float_as_int(w));
    }
}

// ---------------- MMA helpers -------------------------------------------------
__device__ __forceinline__ void ldsm_x4(unsigned& r0, unsigned& r1,
                                        unsigned& r2, unsigned& r3,
                                        unsigned addr) {
    asm volatile("ldmatrix.sync.aligned.m8n8.x4.shared.b16 {%0,%1,%2,%3}, [%4];"
                 : "=r"(r0), "=r"(r1), "=r"(r2), "=r"(r3) : "r"(addr));
}
__device__ __forceinline__ void ldsm_x4_t(unsigned& r0, unsigned& r1,
                                          unsigned& r2, unsigned& r3,
                                          unsigned addr) {
    asm volatile("ldmatrix.sync.aligned.m8n8.x4.trans.shared.b16 {%0,%1,%2,%3}, [%4];"
                 : "=r"(r0), "=r"(r1), "=r"(r2), "=r"(r3) : "r"(addr));
}
__device__ __forceinline__ void mma16816(float* c, const unsigned* a,
                                         const unsigned* b) {
    asm volatile(
        "mma.sync.aligned.m16n8k16.row.col.f32.f16.f16.f32 "
        "{%0,%1,%2,%3}, {%4,%5,%6,%7}, {%8,%9}, {%0,%1,%2,%3};"
        : "+f"(c[0]), "+f"(c[1]), "+f"(c[2]), "+f"(c[3])
        : "r"(a[0]), "r"(a[1]), "r"(a[2]), "r"(a[3]), "r"(b[0]), "r"(b[1]));
}
__device__ __forceinline__ unsigned h2u(__half2 h) {
    return *reinterpret_cast<unsigned*>(&h);
}

// ---------------- tensor-core GEMM -------------------------------------------
// mode 1: A fp32, B=[W1|Wl|Ws]; c<192 -> HS1h, c>=192 -> HSELFh = v + bs
// mode 2: A fp16 (HNEWh), B=W2; -> HS2h
#define GBM 128
#define GBN 64
__global__ __launch_bounds__(256) void k_gemm_mma(const void* __restrict__ Ap,
                                                  const float* __restrict__ W1p,
                                                  const float* __restrict__ Wlp,
                                                  const float* __restrict__ Wsp,
                                                  int M, int Ncols, int mode,
                                                  const float* __restrict__ bs) {
    extern __shared__ __half smemh[];
    __half* Ah = smemh;                 // [128][128] halves, 16B-unit swizzle
    __half* Bh = smemh + GBM * FK;      // [128][64]

    int tid = threadIdx.x;
    int lane = tid & 31, wid = tid >> 5;
    int warp_m = wid & 3, warp_n = wid >> 2;
    int bm = blockIdx.y * GBM, bn = blockIdx.x * GBN;

    // ---- stage A ----
    if (mode == 1) {
        const float* A = (const float*)Ap;
        #pragma unroll
        for (int l = 0; l < 8; l++) {
            int idx = tid + l * 256;                 // 0..2047
            int row = idx >> 4, u = idx & 15;        // unit = 8 halves
            int gr = bm + row;
            float4 f0 = make_float4(0.f, 0.f, 0.f, 0.f);
            float4 f1 = make_float4(0.f, 0.f, 0.f, 0.f);
            if (gr < M) {
                f0 = *(const float4*)&A[gr * FK + u * 8];
                f1 = *(const float4*)&A[gr * FK + u * 8 + 4];
            }
            uint4 p;
            p.x = h2u(__floats2half2_rn(f0.x, f0.y));
            p.y = h2u(__floats2half2_rn(f0.z, f0.w));
            p.z = h2u(__floats2half2_rn(f1.x, f1.y));
            p.w = h2u(__floats2half2_rn(f1.z, f1.w));
            *(uint4*)&Ah[row * FK + ((u ^ (row & 7)) << 3)] = p;
        }
    } else {
        const __half* A = (const __half*)Ap;
        #pragma unroll
        for (int l = 0; l < 8; l++) {
            int idx = tid + l * 256;
            int row = idx >> 4, u = idx & 15;
            int gr = bm + row;
            uint4 p = make_uint4(0u, 0u, 0u, 0u);
            if (gr < M) p = *(const uint4*)&A[gr * FK + u * 8];
            *(uint4*)&Ah[row * FK + ((u ^ (row & 7)) << 3)] = p;
        }
    }
    // ---- stage B: 128x64 fp32 -> fp16 ----
    #pragma unroll
    for (int l = 0; l < 4; l++) {
        int idx = tid + l * 256;                 // 0..1023
        int row = idx >> 3, u = idx & 7;
        int gc = bn + u * 8;
        float4 f0, f1;
        if (mode == 1) {
            f0 = (gc < 128)      ? *(const float4*)&W1p[row * 128 + gc]
               : (gc < 192)      ? *(const float4*)&Wlp[row * 64 + (gc - 128)]
                                 : *(const float4*)&Wsp[row * 128 + (gc - 192)];
            int gc4 = gc + 4;
            f1 = (gc4 < 128)     ? *(const float4*)&W1p[row * 128 + gc4]
               : (gc4 < 192)     ? *(const float4*)&Wlp[row * 64 + (gc4 - 128)]
                                 : *(const float4*)&Wsp[row * 128 + (gc4 - 192)];
        } else {
            f0 = *(const float4*)&W1p[row * 128 + gc];
            f1 = *(const float4*)&W1p[row * 128 + gc + 4];
        }
        uint4 p;
        p.x = h2u(__floats2half2_rn(f0.x, f0.y));
        p.y = h2u(__floats2half2_rn(f0.z, f0.w));
        p.z = h2u(__floats2half2_rn(f1.x, f1.y));
        p.w = h2u(__floats2half2_rn(f1.z, f1.w));
        *(uint4*)&Bh[row * GBN + ((u ^ (row & 7)) << 3)] = p;
    }
    __syncthreads();

    unsigned aBase = (unsigned)__cvta_generic_to_shared(Ah);
    unsigned bBase = (unsigned)__cvta_generic_to_shared(Bh);

    float acc[2][4][4];
    #pragma unroll
    for (int i = 0; i < 2; i++)
        #pragma unroll
        for (int j = 0; j < 4; j++)
            #pragma unroll
            for (int q = 0; q < 4; q++) acc[i][j][q] = 0.0f;

    #pragma unroll
    for (int kc = 0; kc < 8; kc++) {
        int k0 = kc * 16;
        unsigned afr[2][4], bfr[4][2];
        #pragma unroll
        for (int mt = 0; mt < 2; mt++) {
            int lrow = warp_m * 32 + mt * 16 + (lane & 15);
            int lu = (k0 >> 3) + (lane >> 4);
            unsigned addr = aBase + (unsigned)((lrow * FK + ((lu ^ (lrow & 7)) << 3)) * 2);
            ldsm_x4(afr[mt][0], afr[mt][1], afr[mt][2], afr[mt][3], addr);
        }
        #pragma unroll
        for (int np = 0; np < 2; np++) {
            int nb = warp_n * 32 + np * 16;
            int brow = k0 + (lane & 15);
            int bu = (nb >> 3) + (lane >> 4);
            unsigned addr = bBase + (unsigned)((brow * GBN + ((bu ^ (brow & 7)) << 3)) * 2);
            unsigned r0, r1, r2, r3;
            ldsm_x4_t(r0, r1, r2, r3, addr);
            bfr[np * 2][0] = r0;     bfr[np * 2][1] = r1;
            bfr[np * 2 + 1][0] = r2; bfr[np * 2 + 1][1] = r3;
        }
        #pragma unroll
        for (int mt = 0; mt < 2; mt++)
            #pragma unroll
            for (int nt = 0; nt < 4; nt++)
                mma16816(acc[mt][nt], afr[mt], bfr[nt]);
    }

    // ---- epilogue ----
    #pragma unroll
    for (int mt = 0; mt < 2; mt++) {
        int r0 = bm + warp_m * 32 + mt * 16 + (lane >> 2);
        int r1 = r0 + 8;
        #pragma unroll
        for (int nt = 0; nt < 4; nt++) {
            int col = bn + warp_n * 32 + nt * 8 + (lane & 3) * 2;
            float* c = acc[mt][nt];
            if (mode == 1) {
                if (col < C1) {
                    if (r0 < M) *(unsigned*)&g_HS1h[r0 * C1 + col] =
                        h2u(__floats2half2_rn(c[0], c[1]));
                    if (r1 < M) *(unsigned*)&g_HS1h[r1 * C1 + col] =
                        h2u(__floats2half2_rn(c[2], c[3]));
                } else {
                    int cc = col - C1;
                    float bsv0 = bs[cc], bsv1 = bs[cc + 1];
                    if (r0 < M) *(unsigned*)&g_HSELFh[r0 * C2 + cc] =
                        h2u(__floats2half2_rn(c[0] + bsv0, c[1] + bsv1));
                    if (r1 < M) *(unsigned*)&g_HSELFh[r1 * C2 + cc] =
                        h2u(__floats2half2_rn(c[2] + bsv0, c[3] + bsv1));
                }
            } else {
                if (r0 < M) *(unsigned*)&g_HS2h[r0 * C2 + col] =
                    h2u(__floats2half2_rn(c[0], c[1]));
                if (r1 < M) *(unsigned*)&g_HS2h[r1 * C2 + col] =
                    h2u(__floats2half2_rn(c[2], c[3]));
            }
        }
    }
}

// ---------------- gather pass 1: 96 threads, thread t owns cols 2t,2t+1 ------
// 3 warps/block -> 21 blocks/SM. Threads 0-63 = conv1 cols, 64-95 = leader
// cols (warp 2: leader reduction is one warp shuffle). Single int2 rowpair
// load; no leading barrier on the first chunk.
__global__ __launch_bounds__(96) void k_gather1(const float* __restrict__ b1,
                                                const float* __restrict__ bl,
                                                const float* __restrict__ Wl2,
                                                const float* __restrict__ bl2,
                                                float* __restrict__ out) {
    __shared__ int   s_src[96];
    __shared__ float s_w[96];
    __shared__ float s_ls;
    int row = blockIdx.x;
    int t = threadIdx.x;
    int2 rp = g_rowpair[row];
    int beg = rp.x, end = rp.y;

    float di = g_dinv[row];
    float2 f0 = __half22float2(*(const __half2*)&g_HS1h[row * C1 + t * 2]);
    float ax = di * f0.x, ay = di * f0.y;          // self term

    for (int chunk = beg; chunk < end; chunk += 96) {
        int m = min(96, end - chunk);
        if (chunk > beg) __syncthreads();          // protect smem reuse only
        if (t < m) {
            int2 e = g_csr[chunk + t];
            s_src[t] = e.x;
            s_w[t] = __int_as_float(e.y);
        }
        __syncthreads();
        #pragma unroll 4
        for (int j = 0; j < m; j++) {
            float w = s_w[j];
            float2 f = __half22float2(
                *(const __half2*)&g_HS1h[s_src[j] * C1 + t * 2]);
            ax = fmaf(w, f.x, ax); ay = fmaf(w, f.y, ay);
        }
    }

    if (t >= 64) {                                 // leader cols (warp 2)
        int c = t - 64;                            // 0..31 -> cols 128+2c
        float rx = fmaxf(di * ax + bl[2 * c], 0.0f);
        float ry = fmaxf(di * ay + bl[2 * c + 1], 0.0f);
        float p = rx * Wl2[2 * c] + ry * Wl2[2 * c + 1];
        #pragma unroll
        for (int o = 16; o > 0; o >>= 1)
            p += __shfl_down_sync(0xffffffffu, p, o);
        if (c == 0) {
            float z = p + bl2[0];
            float ls = 1.0f / (1.0f + expf(-z));
            s_ls = ls;
            out[NN * 128 + row] = ls;              // leader_score output
        }
    }
    __syncthreads();
    if (t < 64) {                                  // conv1 cols -> HNEW
        float ls = s_ls;
        float hn0 = fmaxf(di * ax + b1[2 * t], 0.0f);
        float hn1 = fmaxf(di * ay + b1[2 * t + 1], 0.0f);
        float2 hs = __half22float2(*(const __half2*)&g_HSELFh[row * C2 + 2 * t]);
        float v0 = (1.0f - ls) * hn0 + ls * hs.x;
        float v1 = (1.0f - ls) * hn1 + ls * hs.y;
        *(__half2*)&g_HNEWh[row * C2 + 2 * t] = __floats2half2_rn(v0, v1);
    }
}

// ---------------- gather pass 2: 64 threads, thread t owns cols 2t,2t+1 ------
// 2 warps/block -> 32 blocks/SM (CTA cap). No cross-thread reduction.
__global__ __launch_bounds__(64) void k_gather2(const float* __restrict__ b2,
                                                float* __restrict__ out) {
    __shared__ int   s_src[64];
    __shared__ float s_w[64];
    int row = blockIdx.x;
    int t = threadIdx.x;
    int2 rp = g_rowpair[row];
    int beg = rp.x, end = rp.y;

    float di = g_dinv[row];
    float2 f0 = __half22float2(*(const __half2*)&g_HS2h[row * C2 + t * 2]);
    float ax = di * f0.x, ay = di * f0.y;

    for (int chunk = beg; chunk < end; chunk += 64) {
        int m = min(64, end - chunk);
        if (chunk > beg) __syncthreads();
        if (t < m) {
            int2 e = g_csr[chunk + t];
            s_src[t] = e.x;
            s_w[t] = __int_as_float(e.y);
        }
        __syncthreads();
        #pragma unroll 4
        for (int j = 0; j < m; j++) {
            float w = s_w[j];
            float2 f = __half22float2(
                *(const __half2*)&g_HS2h[s_src[j] * C2 + t * 2]);
            ax = fmaf(w, f.x, ax); ay = fmaf(w, f.y, ay);
        }
    }

    float2 r;
    r.x = fmaxf(di * ax + b2[2 * t], 0.0f);
    r.y = fmaxf(di * ay + b2[2 * t + 1], 0.0f);
    *(float2*)&out[row * C2 + 2 * t] = r;
}

// ---------------- launch ------------------------------------------------------
extern "C" void kernel_launch(void* const* d_in, const int* in_sizes, int n_in,
                              void* d_out, int out_size) {
    const float* x   = (const float*)d_in[0];
    const int*   ei  = (const int*)d_in[1];        // int32 (JAX x64 disabled)
    const float* ew  = (const float*)d_in[2];
    const float* W1  = (const float*)d_in[3];
    const float* b1  = (const float*)d_in[4];
    const float* W2  = (const float*)d_in[5];
    const float* b2  = (const float*)d_in[6];
    const float* Ws  = (const float*)d_in[7];
    const float* bs  = (const float*)d_in[8];
    const float* Wl  = (const float*)d_in[9];
    const float* bl  = (const float*)d_in[10];
    const float* Wl2 = (const float*)d_in[11];
    const float* bl2 = (const float*)d_in[12];
    float* out = (float*)d_out;

    __half* gHNEWh; cudaGetSymbolAddress((void**)&gHNEWh, g_HNEWh);

    const int SMEM_GEMM = (GBM * FK + FK * GBN) * 2;   // 49152 B

    static cudaStream_t s2 = nullptr;
    static cudaEvent_t evFork = nullptr, evJoin = nullptr;
    if (s2 == nullptr) {
        cudaStreamCreateWithFlags(&s2, cudaStreamNonBlocking);
        cudaEventCreateWithFlags(&evFork, cudaEventDisableTiming);
        cudaEventCreateWithFlags(&evJoin, cudaEventDisableTiming);
        cudaFuncSetAttribute(k_gemm_mma,
                             cudaFuncAttributeMaxDynamicSharedMemorySize,
                             SMEM_GEMM);
    }

    // fork
    cudaEventRecord(evFork, 0);
    cudaStreamWaitEvent(s2, evFork, 0);

    // side stream preproc, main stream GEMM1 in parallel
    k_init<<<(NN + 255) / 256, 256, 0, s2>>>();
    k_deg_hist<<<(EE + 255) / 256, 256, 0, s2>>>(ei, ew);
    kA_scan<<<NB, 256, 0, s2>>>();                       // + dinv fold

    {   // GEMM1: x @ [W1|Wl|Ws] — tensor cores
        dim3 grid(NC / GBN, (NN + GBM - 1) / GBM);
        k_gemm_mma<<<grid, 256, SMEM_GEMM>>>(x, W1, Wl, Ws, NN, NC, 1, bs);
    }

    kB_scan<<<1, 256, 0, s2>>>();
    kC_finalize_ptr<<<(NN + 255) / 256, 256, 0, s2>>>();
    k_fill<<<(EE + 255) / 256, 256, 0, s2>>>(ei, ew);
    cudaEventRecord(evJoin, s2);
    cudaStreamWaitEvent(0, evJoin, 0);

    // gather 1 (96 thr/row; fused relu, leader score, gate; fp16 HNEW)
    k_gather1<<<NN, 96>>>(b1, bl, Wl2, bl2, out);

    // GEMM2: h_new(fp16) @ W2 — tensor cores
    {
        dim3 grid(C2 / GBN, (NN + GBM - 1) / GBM);
        k_gemm_mma<<<grid, 256, SMEM_GEMM>>>(gHNEWh, W2, W2, W2, NN, C2, 2, nullptr);
    }

    // gather 2 (64 thr/row; fused final relu)
    k_gather2<<<NN, 64>>>(b2, out);
}

// round 17
// speedup vs baseline: 1.4270x; 1.0053x over previous
#include <cuda_runtime.h>
#include <cuda_fp16.h>

#define NN 50000
#define EE 800000
#define FK 128          // inner dim
#define C1 192          // agg width pass 1 (128 conv1 + 64 leader)
#define C2 128          // agg width pass 2
#define NC 320          // fused GEMM1 cols: [W1(128) | Wl(64) | Ws(128)]
#define NB 196          // ceil(NN/256)

// ---------------- scratch (device globals; no allocations allowed) -----------
__device__ float g_deg[NN];
__device__ float g_dinv[NN];
__device__ int   g_cnt[NN];
__device__ int   g_rexcl[NN];
__device__ int   g_bsum[NB];
__device__ int   g_boff[NB];
__device__ __align__(8) int2 g_rowpair[NN];           // {beg, end} per row
__device__ int   g_pos[NN];
__device__ __align__(16) int2   g_csr[EE];            // {src, w*dinv[src] bits}
__device__ __align__(16) __half g_HS1h[NN * C1];      // fp16 GEMM1 out (raw)
__device__ __align__(16) __half g_HSELFh[NN * C2];    // x@Ws + bs (fp16)
__device__ __align__(16) __half g_HNEWh[NN * C2];     // gated fusion (fp16)
__device__ __align__(16) __half g_HS2h[NN * C2];      // fp16 GEMM2 out (raw)

// ---------------- degree / histogram -----------------------------------------
__global__ void k_init() {
    int i = blockIdx.x * blockDim.x + threadIdx.x;
    if (i < NN) { g_deg[i] = 1.0f; g_cnt[i] = 0; }     // self-loop weight 1
}

__global__ void k_deg_hist(const int* __restrict__ ei,
                           const float* __restrict__ ew) {
    int e = blockIdx.x * blockDim.x + threadIdx.x;
    if (e < EE) {
        int d = ei[EE + e];
        atomicAdd(&g_deg[d], ew[e]);
        atomicAdd(&g_cnt[d], 1);
    }
}

// ---------------- hierarchical exclusive scan of g_cnt (+ dinv fold) ---------
__device__ __forceinline__ int block_scan256(int v, int t, int* total) {
    int lane = t & 31, w = t >> 5;
    int x = v;
    #pragma unroll
    for (int o = 1; o < 32; o <<= 1) {
        int y = __shfl_up_sync(0xffffffffu, x, o);
        if (lane >= o) x += y;
    }
    __shared__ int ws[8];
    if (lane == 31) ws[w] = x;
    __syncthreads();
    if (t < 8) {
        int z = ws[t];
        #pragma unroll
        for (int o = 1; o < 8; o <<= 1) {
            int q = __shfl_up_sync(0xffu, z, o);
            if (t >= o) z += q;
        }
        ws[t] = z;
    }
    __syncthreads();
    int woff = (w > 0) ? ws[w - 1] : 0;
    *total = ws[7];
    return woff + x - v;           // exclusive prefix
}

__global__ __launch_bounds__(256) void kA_scan() {
    int b = blockIdx.x, t = threadIdx.x;
    int i = b * 256 + t;
    int v = (i < NN) ? g_cnt[i] : 0;
    int total;
    int excl = block_scan256(v, t, &total);
    if (i < NN) {
        g_rexcl[i] = excl;
        float dg = g_deg[i];
        g_dinv[i] = dg > 0.0f ? rsqrtf(dg) : 0.0f;     // dinv folded here
    }
    if (t == 0) g_bsum[b] = total;
}

__global__ __launch_bounds__(256) void kB_scan() {
    int t = threadIdx.x;
    int v = (t < NB) ? g_bsum[t] : 0;
    int total;
    int excl = block_scan256(v, t, &total);
    if (t < NB) g_boff[t] = excl;
}

__global__ void kC_finalize_ptr() {
    int i = blockIdx.x * blockDim.x + threadIdx.x;
    if (i < NN) {
        int r = g_rexcl[i] + g_boff[i >> 8];
        g_rowpair[i].x = r;
        if (i > 0) g_rowpair[i - 1].y = r;
        if (i == NN - 1) g_rowpair[NN - 1].y = EE;
        g_pos[i] = r;
    }
}

__global__ void k_fill(const int* __restrict__ ei,
                       const float* __restrict__ ew) {
    int e = blockIdx.x * blockDim.x + threadIdx.x;
    if (e < EE) {
        int s = ei[e];
        int d = ei[EE + e];
        int p = atomicAdd(&g_pos[d], 1);
        float w = ew[e] * g_dinv[s];       // fold dinv[src]
        g_csr[p] = make_int2(s, __float_as_int(w));
    }
}

// ---------------- MMA helpers -------------------------------------------------
__device__ __forceinline__ void ldsm_x4(unsigned& r0, unsigned& r1,
                                        unsigned& r2, unsigned& r3,
                                        unsigned addr) {
    asm volatile("ldmatrix.sync.aligned.m8n8.x4.shared.b16 {%0,%1,%2,%3}, [%4];"
                 : "=r"(r0), "=r"(r1), "=r"(r2), "=r"(r3) : "r"(addr));
}
__device__ __forceinline__ void ldsm_x4_t(unsigned& r0, unsigned& r1,
                                          unsigned& r2, unsigned& r3,
                                          unsigned addr) {
    asm volatile("ldmatrix.sync.aligned.m8n8.x4.trans.shared.b16 {%0,%1,%2,%3}, [%4];"
                 : "=r"(r0), "=r"(r1), "=r"(r2), "=r"(r3) : "r"(addr));
}
__device__ __forceinline__ void mma16816(float* c, const unsigned* a,
                                         const unsigned* b) {
    asm volatile(
        "mma.sync.aligned.m16n8k16.row.col.f32.f16.f16.f32 "
        "{%0,%1,%2,%3}, {%4,%5,%6,%7}, {%8,%9}, {%0,%1,%2,%3};"
        : "+f"(c[0]), "+f"(c[1]), "+f"(c[2]), "+f"(c[3])
        : "r"(a[0]), "r"(a[1]), "r"(a[2]), "r"(a[3]), "r"(b[0]), "r"(b[1]));
}
__device__ __forceinline__ unsigned h2u(__half2 h) {
    return *reinterpret_cast<unsigned*>(&h);
}

// ---------------- tensor-core GEMM (A staged once, N-tile loop) --------------
// mode 1: A fp32, B=[W1|Wl|Ws]; c<192 -> HS1h, c>=192 -> HSELFh = v + bs
// mode 2: A fp16 (HNEWh), B=W2; -> HS2h
// Grid = (1, ceil(M/GBM)); block loops over Ncols in GBN steps.
#define GBM 128
#define GBN 64
__global__ __launch_bounds__(256) void k_gemm_mma(const void* __restrict__ Ap,
                                                  const float* __restrict__ W1p,
                                                  const float* __restrict__ Wlp,
                                                  const float* __restrict__ Wsp,
                                                  int M, int Ncols, int mode,
                                                  const float* __restrict__ bs) {
    extern __shared__ __half smemh[];
    __half* Ah = smemh;                 // [128][128] halves, 16B-unit swizzle
    __half* Bh = smemh + GBM * FK;      // [128][64]

    int tid = threadIdx.x;
    int lane = tid & 31, wid = tid >> 5;
    int warp_m = wid & 3, warp_n = wid >> 2;
    int bm = blockIdx.y * GBM;

    // ---- stage A once ----
    if (mode == 1) {
        const float* A = (const float*)Ap;
        #pragma unroll
        for (int l = 0; l < 8; l++) {
            int idx = tid + l * 256;                 // 0..2047
            int row = idx >> 4, u = idx & 15;        // unit = 8 halves
            int gr = bm + row;
            float4 f0 = make_float4(0.f, 0.f, 0.f, 0.f);
            float4 f1 = make_float4(0.f, 0.f, 0.f, 0.f);
            if (gr < M) {
                f0 = *(const float4*)&A[gr * FK + u * 8];
                f1 = *(const float4*)&A[gr * FK + u * 8 + 4];
            }
            uint4 p;
            p.x = h2u(__floats2half2_rn(f0.x, f0.y));
            p.y = h2u(__floats2half2_rn(f0.z, f0.w));
            p.z = h2u(__floats2half2_rn(f1.x, f1.y));
            p.w = h2u(__floats2half2_rn(f1.z, f1.w));
            *(uint4*)&Ah[row * FK + ((u ^ (row & 7)) << 3)] = p;
        }
    } else {
        const __half* A = (const __half*)Ap;
        #pragma unroll
        for (int l = 0; l < 8; l++) {
            int idx = tid + l * 256;
            int row = idx >> 4, u = idx & 15;
            int gr = bm + row;
            uint4 p = make_uint4(0u, 0u, 0u, 0u);
            if (gr < M) p = *(const uint4*)&A[gr * FK + u * 8];
            *(uint4*)&Ah[row * FK + ((u ^ (row & 7)) << 3)] = p;
        }
    }

    unsigned aBase = (unsigned)__cvta_generic_to_shared(Ah);
    unsigned bBase = (unsigned)__cvta_generic_to_shared(Bh);

    for (int bn = 0; bn < Ncols; bn += GBN) {
        // protect Bh reuse (first iteration: also covers A staging)
        __syncthreads();

        // ---- stage B tile: 128 x 64 fp32 -> fp16 ----
        #pragma unroll
        for (int l = 0; l < 4; l++) {
            int idx = tid + l * 256;             // 0..1023
            int row = idx >> 3, u = idx & 7;
            int gc = bn + u * 8;
            float4 f0, f1;
            if (mode == 1) {
                f0 = (gc < 128)      ? *(const float4*)&W1p[row * 128 + gc]
                   : (gc < 192)      ? *(const float4*)&Wlp[row * 64 + (gc - 128)]
                                     : *(const float4*)&Wsp[row * 128 + (gc - 192)];
                int gc4 = gc + 4;
                f1 = (gc4 < 128)     ? *(const float4*)&W1p[row * 128 + gc4]
                   : (gc4 < 192)     ? *(const float4*)&Wlp[row * 64 + (gc4 - 128)]
                                     : *(const float4*)&Wsp[row * 128 + (gc4 - 192)];
            } else {
                f0 = *(const float4*)&W1p[row * 128 + gc];
                f1 = *(const float4*)&W1p[row * 128 + gc + 4];
            }
            uint4 p;
            p.x = h2u(__floats2half2_rn(f0.x, f0.y));
            p.y = h2u(__floats2half2_rn(f0.z, f0.w));
            p.z = h2u(__floats2half2_rn(f1.x, f1.y));
            p.w = h2u(__floats2half2_rn(f1.z, f1.w));
            *(uint4*)&Bh[row * GBN + ((u ^ (row & 7)) << 3)] = p;
        }
        __syncthreads();

        float acc[2][4][4];
        #pragma unroll
        for (int i = 0; i < 2; i++)
            #pragma unroll
            for (int j = 0; j < 4; j++)
                #pragma unroll
                for (int q = 0; q < 4; q++) acc[i][j][q] = 0.0f;

        #pragma unroll
        for (int kc = 0; kc < 8; kc++) {
            int k0 = kc * 16;
            unsigned afr[2][4], bfr[4][2];
            #pragma unroll
            for (int mt = 0; mt < 2; mt++) {
                int lrow = warp_m * 32 + mt * 16 + (lane & 15);
                int lu = (k0 >> 3) + (lane >> 4);
                unsigned addr = aBase + (unsigned)((lrow * FK + ((lu ^ (lrow & 7)) << 3)) * 2);
                ldsm_x4(afr[mt][0], afr[mt][1], afr[mt][2], afr[mt][3], addr);
            }
            #pragma unroll
            for (int np = 0; np < 2; np++) {
                int nb = warp_n * 32 + np * 16;
                int brow = k0 + (lane & 15);
                int bu = (nb >> 3) + (lane >> 4);
                unsigned addr = bBase + (unsigned)((brow * GBN + ((bu ^ (brow & 7)) << 3)) * 2);
                unsigned r0, r1, r2, r3;
                ldsm_x4_t(r0, r1, r2, r3, addr);
                bfr[np * 2][0] = r0;     bfr[np * 2][1] = r1;
                bfr[np * 2 + 1][0] = r2; bfr[np * 2 + 1][1] = r3;
            }
            #pragma unroll
            for (int mt = 0; mt < 2; mt++)
                #pragma unroll
                for (int nt = 0; nt < 4; nt++)
                    mma16816(acc[mt][nt], afr[mt], bfr[nt]);
        }

        // ---- epilogue for this N tile (registers/global only) ----
        #pragma unroll
        for (int mt = 0; mt < 2; mt++) {
            int r0 = bm + warp_m * 32 + mt * 16 + (lane >> 2);
            int r1 = r0 + 8;
            #pragma unroll
            for (int nt = 0; nt < 4; nt++) {
                int col = bn + warp_n * 32 + nt * 8 + (lane & 3) * 2;
                float* c = acc[mt][nt];
                if (mode == 1) {
                    if (col < C1) {
                        if (r0 < M) *(unsigned*)&g_HS1h[r0 * C1 + col] =
                            h2u(__floats2half2_rn(c[0], c[1]));
                        if (r1 < M) *(unsigned*)&g_HS1h[r1 * C1 + col] =
                            h2u(__floats2half2_rn(c[2], c[3]));
                    } else {
                        int cc = col - C1;
                        float bsv0 = bs[cc], bsv1 = bs[cc + 1];
                        if (r0 < M) *(unsigned*)&g_HSELFh[r0 * C2 + cc] =
                            h2u(__floats2half2_rn(c[0] + bsv0, c[1] + bsv1));
                        if (r1 < M) *(unsigned*)&g_HSELFh[r1 * C2 + cc] =
                            h2u(__floats2half2_rn(c[2] + bsv0, c[3] + bsv1));
                    }
                } else {
                    if (r0 < M) *(unsigned*)&g_HS2h[r0 * C2 + col] =
                        h2u(__floats2half2_rn(c[0], c[1]));
                    if (r1 < M) *(unsigned*)&g_HS2h[r1 * C2 + col] =
                        h2u(__floats2half2_rn(c[2], c[3]));
                }
            }
        }
    }
}

// ---------------- gather pass 1: 96 threads, thread t owns cols 2t,2t+1 ------
__global__ __launch_bounds__(96) void k_gather1(const float* __restrict__ b1,
                                                const float* __restrict__ bl,
                                                const float* __restrict__ Wl2,
                                                const float* __restrict__ bl2,
                                                float* __restrict__ out) {
    __shared__ int   s_src[96];
    __shared__ float s_w[96];
    __shared__ float s_ls;
    int row = blockIdx.x;
    int t = threadIdx.x;
    int2 rp = g_rowpair[row];
    int beg = rp.x, end = rp.y;

    float di = g_dinv[row];
    float2 f0 = __half22float2(*(const __half2*)&g_HS1h[row * C1 + t * 2]);
    float ax = di * f0.x, ay = di * f0.y;          // self term

    for (int chunk = beg; chunk < end; chunk += 96) {
        int m = min(96, end - chunk);
        if (chunk > beg) __syncthreads();          // protect smem reuse only
        if (t < m) {
            int2 e = g_csr[chunk + t];
            s_src[t] = e.x;
            s_w[t] = __int_as_float(e.y);
        }
        __syncthreads();
        #pragma unroll 4
        for (int j = 0; j < m; j++) {
            float w = s_w[j];
            float2 f = __half22float2(
                *(const __half2*)&g_HS1h[s_src[j] * C1 + t * 2]);
            ax = fmaf(w, f.x, ax); ay = fmaf(w, f.y, ay);
        }
    }

    if (t >= 64) {                                 // leader cols (warp 2)
        int c = t - 64;                            // 0..31 -> cols 128+2c
        float rx = fmaxf(di * ax + bl[2 * c], 0.0f);
        float ry = fmaxf(di * ay + bl[2 * c + 1], 0.0f);
        float p = rx * Wl2[2 * c] + ry * Wl2[2 * c + 1];
        #pragma unroll
        for (int o = 16; o > 0; o >>= 1)
            p += __shfl_down_sync(0xffffffffu, p, o);
        if (c == 0) {
            float z = p + bl2[0];
            float ls = 1.0f / (1.0f + expf(-z));
            s_ls = ls;
            out[NN * 128 + row] = ls;              // leader_score output
        }
    }
    __syncthreads();
    if (t < 64) {                                  // conv1 cols -> HNEW
        float ls = s_ls;
        float hn0 = fmaxf(di * ax + b1[2 * t], 0.0f);
        float hn1 = fmaxf(di * ay + b1[2 * t + 1], 0.0f);
        float2 hs = __half22float2(*(const __half2*)&g_HSELFh[row * C2 + 2 * t]);
        float v0 = (1.0f - ls) * hn0 + ls * hs.x;
        float v1 = (1.0f - ls) * hn1 + ls * hs.y;
        *(__half2*)&g_HNEWh[row * C2 + 2 * t] = __floats2half2_rn(v0, v1);
    }
}

// ---------------- gather pass 2: 64 threads, thread t owns cols 2t,2t+1 ------
__global__ __launch_bounds__(64) void k_gather2(const float* __restrict__ b2,
                                                float* __restrict__ out) {
    __shared__ int   s_src[64];
    __shared__ float s_w[64];
    int row = blockIdx.x;
    int t = threadIdx.x;
    int2 rp = g_rowpair[row];
    int beg = rp.x, end = rp.y;

    float di = g_dinv[row];
    float2 f0 = __half22float2(*(const __half2*)&g_HS2h[row * C2 + t * 2]);
    float ax = di * f0.x, ay = di * f0.y;

    for (int chunk = beg; chunk < end; chunk += 64) {
        int m = min(64, end - chunk);
        if (chunk > beg) __syncthreads();
        if (t < m) {
            int2 e = g_csr[chunk + t];
            s_src[t] = e.x;
            s_w[t] = __int_as_float(e.y);
        }
        __syncthreads();
        #pragma unroll 4
        for (int j = 0; j < m; j++) {
            float w = s_w[j];
            float2 f = __half22float2(
                *(const __half2*)&g_HS2h[s_src[j] * C2 + t * 2]);
            ax = fmaf(w, f.x, ax); ay = fmaf(w, f.y, ay);
        }
    }

    float2 r;
    r.x = fmaxf(di * ax + b2[2 * t], 0.0f);
    r.y = fmaxf(di * ay + b2[2 * t + 1], 0.0f);
    *(float2*)&out[row * C2 + 2 * t] = r;
}

// ---------------- launch ------------------------------------------------------
extern "C" void kernel_launch(void* const* d_in, const int* in_sizes, int n_in,
                              void* d_out, int out_size) {
    const float* x   = (const float*)d_in[0];
    const int*   ei  = (const int*)d_in[1];        // int32 (JAX x64 disabled)
    const float* ew  = (const float*)d_in[2];
    const float* W1  = (const float*)d_in[3];
    const float* b1  = (const float*)d_in[4];
    const float* W2  = (const float*)d_in[5];
    const float* b2  = (const float*)d_in[6];
    const float* Ws  = (const float*)d_in[7];
    const float* bs  = (const float*)d_in[8];
    const float* Wl  = (const float*)d_in[9];
    const float* bl  = (const float*)d_in[10];
    const float* Wl2 = (const float*)d_in[11];
    const float* bl2 = (const float*)d_in[12];
    float* out = (float*)d_out;

    __half* gHNEWh; cudaGetSymbolAddress((void**)&gHNEWh, g_HNEWh);

    const int SMEM_GEMM = (GBM * FK + FK * GBN) * 2;   // 49152 B

    static cudaStream_t s2 = nullptr;
    static cudaEvent_t evFork = nullptr, evJoin = nullptr;
    if (s2 == nullptr) {
        cudaStreamCreateWithFlags(&s2, cudaStreamNonBlocking);
        cudaEventCreateWithFlags(&evFork, cudaEventDisableTiming);
        cudaEventCreateWithFlags(&evJoin, cudaEventDisableTiming);
        cudaFuncSetAttribute(k_gemm_mma,
                             cudaFuncAttributeMaxDynamicSharedMemorySize,
                             SMEM_GEMM);
    }

    // fork
    cudaEventRecord(evFork, 0);
    cudaStreamWaitEvent(s2, evFork, 0);

    // side stream preproc, main stream GEMM1 in parallel
    k_init<<<(NN + 255) / 256, 256, 0, s2>>>();
    k_deg_hist<<<(EE + 255) / 256, 256, 0, s2>>>(ei, ew);
    kA_scan<<<NB, 256, 0, s2>>>();                       // + dinv fold

    {   // GEMM1: x @ [W1|Wl|Ws] — tensor cores, A staged once
        dim3 grid(1, (NN + GBM - 1) / GBM);
        k_gemm_mma<<<grid, 256, SMEM_GEMM>>>(x, W1, Wl, Ws, NN, NC, 1, bs);
    }

    kB_scan<<<1, 256, 0, s2>>>();
    kC_finalize_ptr<<<(NN + 255) / 256, 256, 0, s2>>>();
    k_fill<<<(EE + 255) / 256, 256, 0, s2>>>(ei, ew);
    cudaEventRecord(evJoin, s2);
    cudaStreamWaitEvent(0, evJoin, 0);

    // gather 1 (96 thr/row; fused relu, leader score, gate; fp16 HNEW)
    k_gather1<<<NN, 96>>>(b1, bl, Wl2, bl2, out);

    // GEMM2: h_new(fp16) @ W2 — tensor cores, A staged once
    {
        dim3 grid(1, (NN + GBM - 1) / GBM);
        k_gemm_mma<<<grid, 256, SMEM_GEMM>>>(gHNEWh, W2, W2, W2, NN, C2, 2, nullptr);
    }

    // gather 2 (64 thr/row; fused final relu)
    k_gather2<<<NN, 64>>>(b2, out);
}